// round 14
// baseline (speedup 1.0000x reference)
#include <cuda_runtime.h>
#include <cstdint>

// ---------------- problem dimensions (fixed by the dataset) ----------------
#define M_DIM 16384   // 4 * 4096 tokens
#define D_DIM 1024
#define H_DIM 4096

// NOTE (env, R2): harness PTX target is sm_103 (no 'a') -> no tcgen05/TMEM.
// NOTE (R5): h must stay fp32 (fp16 h -> rel_err 1.9e-3 FAIL).
// NOTE (R10): forced mma+dp4a co-residency REGRESSED; same-kind pairing (mod-8
//   hash) is required for the hybrid win.
// NOTE (R13 profile): production GEMM1 runs at 296 MACs/cyc/SM chip-wide,
//   ABOVE the pure-mma pipe rate (290) -> the dp4a path is at least as fast
//   as mma on this part (old rt=2 model falsified).
// THIS ROUND: exact R12 source, ONE change: kind split 62.5/37.5 -> 50/50
//   (((bn+bm)&7)<4). If dp4a >= mma, feeding it more tiles raises the blend.

// ---------------- device scratch (static, allocation-free) ----------------
__device__ __align__(128) int8_t  g_xq[(size_t)M_DIM * D_DIM];     // 16 MB
__device__ __align__(128) int8_t  g_hq[(size_t)M_DIM * H_DIM];     // 64 MB
__device__ __align__(128) float   g_h [(size_t)M_DIM * H_DIM];     // 256 MB
__device__ __align__(128) int8_t  g_w1q[(size_t)H_DIM * D_DIM];    // 4 MB
__device__ __align__(128) int8_t  g_w2q[(size_t)D_DIM * H_DIM];    // 4 MB
__device__ int     g_rs1[H_DIM];
__device__ int     g_rs2[D_DIM];
// stats: 0=min_x(enc) 1=max_x(enc) 2=absmax_w1 3=absmax_w2 4=min_h(enc) 5=max_h(enc)
__device__ unsigned g_stats[6];
// scales: 0=sx 1=sw1 2=sw2 3=s1(sx*sw1) 4=sh 5=s2(sh*sw2)
__device__ float    g_scale[6];
__device__ int      g_zp[2];   // 0=zx 1=zh

// ---------------- helpers ----------------
__device__ __forceinline__ unsigned fenc(float f) {
    unsigned u = __float_as_uint(f);
    return (u & 0x80000000u) ? ~u : (u | 0x80000000u);
}
__device__ __forceinline__ float fdec(unsigned e) {
    return __uint_as_float((e & 0x80000000u) ? (e ^ 0x80000000u) : ~e);
}
__device__ __forceinline__ float gelu_exact(float v) {
    return 0.5f * v * (1.0f + erff(v * 0.7071067811865476f));
}
__device__ __forceinline__ uint32_t smem_u32(const void* p) {
    uint32_t a;
    asm("{ .reg .u64 t; cvta.to.shared.u64 t, %1; cvt.u32.u64 %0, t; }" : "=r"(a) : "l"(p));
    return a;
}
__device__ __forceinline__ int dp4a(int a, int b, int c) {
    int d;
    asm("dp4a.s32.s32 %0, %1, %2, %3;" : "=r"(d) : "r"(a), "r"(b), "r"(c));
    return d;
}

#define CP_ASYNC16(dst_u32, src_ptr) \
    asm volatile("cp.async.cg.shared.global [%0], [%1], 16;\n" :: "r"(dst_u32), "l"(src_ptr))
#define CP_COMMIT() asm volatile("cp.async.commit_group;\n" ::: "memory")
#define CP_WAIT1()  asm volatile("cp.async.wait_group 1;\n" ::: "memory")

#define SWZ(off) ((off) ^ (((off) >> 3) & 0x70))

#define LDSM_X4(r0, r1, r2, r3, addr) \
    asm volatile("ldmatrix.sync.aligned.m8n8.x4.shared.b16 {%0,%1,%2,%3}, [%4];" \
                 : "=r"(r0), "=r"(r1), "=r"(r2), "=r"(r3) : "r"(addr))

__device__ __forceinline__ void mma_s8(int* c, const uint32_t* a, const uint32_t* b) {
    asm volatile(
        "mma.sync.aligned.m16n8k32.row.col.s32.s8.s8.s32 "
        "{%0,%1,%2,%3}, {%4,%5,%6,%7}, {%8,%9}, {%0,%1,%2,%3};\n"
        : "+r"(c[0]), "+r"(c[1]), "+r"(c[2]), "+r"(c[3])
        : "r"(a[0]), "r"(a[1]), "r"(a[2]), "r"(a[3]), "r"(b[0]), "r"(b[1]));
}

// ---------------- init ----------------
__global__ void k_init() {
    if (threadIdx.x == 0) {
        g_stats[0] = 0xFFFFFFFFu; g_stats[1] = 0u;
        g_stats[2] = 0u;          g_stats[3] = 0u;
        g_stats[4] = 0xFFFFFFFFu; g_stats[5] = 0u;
    }
}

// ---------------- fused stats: minmax(x) || absmax(W1) || absmax(W2) ----------------
static constexpr int STAT_BX = 4096;
static constexpr int STAT_BW = 1024;

__global__ void k_stats(const float4* __restrict__ x, int nx4,
                        const float4* __restrict__ w1, int n14,
                        const float4* __restrict__ w2, int n24) {
    const int b = blockIdx.x;
    __shared__ float sm[2][8];
    if (b < STAT_BX) {
        float lmin = 3.4e38f, lmax = -3.4e38f;
        for (int i = b * blockDim.x + threadIdx.x; i < nx4; i += STAT_BX * blockDim.x) {
            float4 v = x[i];
            lmin = fminf(lmin, fminf(fminf(v.x, v.y), fminf(v.z, v.w)));
            lmax = fmaxf(lmax, fmaxf(fmaxf(v.x, v.y), fmaxf(v.z, v.w)));
        }
        #pragma unroll
        for (int o = 16; o; o >>= 1) {
            lmin = fminf(lmin, __shfl_xor_sync(0xffffffffu, lmin, o));
            lmax = fmaxf(lmax, __shfl_xor_sync(0xffffffffu, lmax, o));
        }
        if ((threadIdx.x & 31) == 0) { sm[0][threadIdx.x >> 5] = lmin; sm[1][threadIdx.x >> 5] = lmax; }
        __syncthreads();
        if (threadIdx.x == 0) {
            float m = sm[0][0], M = sm[1][0];
            #pragma unroll
            for (int w = 1; w < 8; w++) { m = fminf(m, sm[0][w]); M = fmaxf(M, sm[1][w]); }
            atomicMin(&g_stats[0], fenc(m));
            atomicMax(&g_stats[1], fenc(M));
        }
    } else {
        const int which = (b < STAT_BX + STAT_BW) ? 0 : 1;
        const int b0 = which ? (STAT_BX + STAT_BW) : STAT_BX;
        const float4* w = which ? w2 : w1;
        const int n4 = which ? n24 : n14;
        const int slot = which ? 3 : 2;
        float lmax = 0.0f;
        for (int i = (b - b0) * blockDim.x + threadIdx.x; i < n4; i += STAT_BW * blockDim.x) {
            float4 v = w[i];
            lmax = fmaxf(lmax, fmaxf(fmaxf(fabsf(v.x), fabsf(v.y)), fmaxf(fabsf(v.z), fabsf(v.w))));
        }
        #pragma unroll
        for (int o = 16; o; o >>= 1) lmax = fmaxf(lmax, __shfl_xor_sync(0xffffffffu, lmax, o));
        if ((threadIdx.x & 31) == 0) sm[0][threadIdx.x >> 5] = lmax;
        __syncthreads();
        if (threadIdx.x == 0) {
            float M = sm[0][0];
            #pragma unroll
            for (int w2i = 1; w2i < 8; w2i++) M = fmaxf(M, sm[0][w2i]);
            atomicMax(&g_stats[slot], __float_as_uint(M));
        }
    }
}

// ---------------- finalize input/weight scales ----------------
__global__ void k_fin1() {
    if (threadIdx.x != 0) return;
    float an = fdec(g_stats[0]), ax = fdec(g_stats[1]);
    float sx = fmaxf(__fdiv_rn(ax - an, 255.0f), 1e-8f);
    float zxf = rintf(__fdiv_rn(-an, sx)) - 128.0f;
    zxf = fminf(fmaxf(zxf, -128.0f), 127.0f);
    float sw1 = fmaxf(__fdiv_rn(__uint_as_float(g_stats[2]), 127.0f), 1e-8f);
    float sw2 = fmaxf(__fdiv_rn(__uint_as_float(g_stats[3]), 127.0f), 1e-8f);
    g_scale[0] = sx; g_scale[1] = sw1; g_scale[2] = sw2;
    g_scale[3] = sx * sw1;
    g_zp[0] = (int)zxf;
}

// ---------------- finalize h scales (after GEMM1) ----------------
__global__ void k_fin2() {
    if (threadIdx.x != 0) return;
    float hn = fdec(g_stats[4]), hx = fdec(g_stats[5]);
    float sh = fmaxf(__fdiv_rn(hx - hn, 255.0f), 1e-8f);
    float zhf = rintf(__fdiv_rn(-hn, sh)) - 128.0f;
    zhf = fminf(fmaxf(zhf, -128.0f), 127.0f);
    g_scale[4] = sh;
    g_scale[5] = sh * g_scale[2];
    g_zp[1] = (int)zhf;
}

// ---------------- fused quantize: x || W1(+rs1) || W2(+rs2) ----------------
static constexpr int QA_BX = 2048;

__global__ void k_quant_all(const float4* __restrict__ x,
                            const float* __restrict__ W1,
                            const float* __restrict__ W2) {
    const int b = blockIdx.x;
    if (b < QA_BX) {
        const size_t n4 = (size_t)M_DIM * D_DIM / 4;
        char4* dst = (char4*)g_xq;
        float s = g_scale[0];
        float zp = (float)g_zp[0];
        for (size_t i = b * (size_t)blockDim.x + threadIdx.x; i < n4;
             i += (size_t)QA_BX * blockDim.x) {
            float4 v = x[i];
            float q0 = fminf(fmaxf(rintf(__fdiv_rn(v.x, s)) + zp, -128.0f), 127.0f);
            float q1 = fminf(fmaxf(rintf(__fdiv_rn(v.y, s)) + zp, -128.0f), 127.0f);
            float q2 = fminf(fmaxf(rintf(__fdiv_rn(v.z, s)) + zp, -128.0f), 127.0f);
            float q3 = fminf(fmaxf(rintf(__fdiv_rn(v.w, s)) + zp, -128.0f), 127.0f);
            char4 c; c.x = (char)(int)q0; c.y = (char)(int)q1; c.z = (char)(int)q2; c.w = (char)(int)q3;
            dst[i] = c;
        }
    } else {
        const int which = (b < QA_BX + H_DIM) ? 0 : 1;
        const int row = which ? (b - QA_BX - H_DIM) : (b - QA_BX);
        const int cols = which ? H_DIM : D_DIM;
        const float* W = which ? W2 : W1;
        int8_t* wq = which ? g_w2q : g_w1q;
        int* rs = which ? g_rs2 : g_rs1;
        float sw = which ? g_scale[2] : g_scale[1];
        const float4* src = (const float4*)(W + (size_t)row * cols);
        char4* dst = (char4*)(wq + (size_t)row * cols);
        int acc = 0;
        for (int c = threadIdx.x; c < (cols >> 2); c += blockDim.x) {
            float4 v = src[c];
            float q0 = fminf(fmaxf(rintf(__fdiv_rn(v.x, sw)), -127.0f), 127.0f);
            float q1 = fminf(fmaxf(rintf(__fdiv_rn(v.y, sw)), -127.0f), 127.0f);
            float q2 = fminf(fmaxf(rintf(__fdiv_rn(v.z, sw)), -127.0f), 127.0f);
            float q3 = fminf(fmaxf(rintf(__fdiv_rn(v.w, sw)), -127.0f), 127.0f);
            int i0 = (int)q0, i1 = (int)q1, i2 = (int)q2, i3 = (int)q3;
            acc += i0 + i1 + i2 + i3;
            char4 cc; cc.x = (char)i0; cc.y = (char)i1; cc.z = (char)i2; cc.w = (char)i3;
            dst[c] = cc;
        }
        #pragma unroll
        for (int o = 16; o; o >>= 1) acc += __shfl_xor_sync(0xffffffffu, acc, o);
        __shared__ int sm[8];
        if ((threadIdx.x & 31) == 0) sm[threadIdx.x >> 5] = acc;
        __syncthreads();
        if (threadIdx.x == 0) {
            int t = 0;
            #pragma unroll
            for (int w = 0; w < 8; w++) t += sm[w];
            rs[row] = t;
        }
    }
}

// ---------------- h quantize (fp32 -> int8) ----------------
__global__ void k_quant_h(size_t n4) {
    const float4* src = (const float4*)g_h;
    char4* dst = (char4*)g_hq;
    float s = g_scale[4];
    float zp = (float)g_zp[1];
    for (size_t i = blockIdx.x * (size_t)blockDim.x + threadIdx.x; i < n4;
         i += (size_t)gridDim.x * blockDim.x) {
        float4 v = src[i];
        float q0 = fminf(fmaxf(rintf(__fdiv_rn(v.x, s)) + zp, -128.0f), 127.0f);
        float q1 = fminf(fmaxf(rintf(__fdiv_rn(v.y, s)) + zp, -128.0f), 127.0f);
        float q2 = fminf(fmaxf(rintf(__fdiv_rn(v.z, s)) + zp, -128.0f), 127.0f);
        float q3 = fminf(fmaxf(rintf(__fdiv_rn(v.w, s)) + zp, -128.0f), 127.0f);
        char4 c; c.x = (char)(int)q0; c.y = (char)(int)q1; c.z = (char)(int)q2; c.w = (char)(int)q3;
        dst[i] = c;
    }
}

// ========== hybrid int8 GEMM, templated M-tile (BM in {128, 64}) ==========
// kind 0 (mma):  16 warps, warp tile (BM/4)x32, 3-stage cp.async
// kind 1 (dp4a): BMx128 tile, K-transposed smem, 2-stage, spill-free
// kind = ((bn+bm)&7)<4 : 50/50 split. GEMM1 co-resident pairs (delta 24 = 0
//   mod 8) remain SAME kind, preserving the segregation R10 showed we need.
static constexpr int SBN = 128;
static constexpr int SBK = 128;
static constexpr int NSTAGE = 3;
static constexpr int GTHREADS = 512;

template <int BM> struct GemmDims {
    static constexpr int IM = BM / 64;
    static constexpr int RPT = BM / 32;
    static constexpr int LOGBM = (BM == 128) ? 7 : 6;
    static constexpr int STAGE_A = BM * SBK;
    static constexpr int STAGE_SZ = STAGE_A + SBN * SBK;
    static constexpr int SMEM_DYN = 1024 + NSTAGE * STAGE_SZ;
    static constexpr int SDP = BM * 32 + 4096;
};

template <int MODE, int BM>
__global__ __launch_bounds__(GTHREADS, 2)
void k_gemm(const float* __restrict__ bias, int N, int K, float* __restrict__ outp) {
    using D = GemmDims<BM>;
    extern __shared__ char dsmem[];
    const int tid = threadIdx.x, wid = tid >> 5, lane = tid & 31;
    const int bm = blockIdx.y, bn = blockIdx.x;

    const int8_t* __restrict__ A = MODE ? g_xq : g_hq;
    const int8_t* __restrict__ B = MODE ? g_w1q : g_w2q;
    const int* __restrict__ rs   = MODE ? g_rs1 : g_rs2;
    float* __restrict__ out      = MODE ? g_h : outp;
    const float sc = MODE ? g_scale[3] : g_scale[5];
    const int   z  = MODE ? g_zp[0] : g_zp[1];

    const uint32_t base0 = smem_u32(dsmem);
    const uint32_t tiles = (base0 + 1023) & ~1023u;
    const int KT = K >> 7;

    const int kind = (((bn + bm) & 7) < 4) ? 0 : 1;

    float lmin = 3.4e38f, lmax = -3.4e38f;

    if (kind == 0) {
        // ================= mma path =================
        const int warp_m = wid & 3;
        const int warp_n = wid >> 2;

        uint32_t offA[D::IM], offB[2];
        {
            int rbase = warp_m * (BM / 4) + (lane & 7) + ((lane >> 3) & 1) * 8;
            int cA = ((lane >> 4) & 1) * 16;
            #pragma unroll
            for (int im = 0; im < D::IM; im++) {
                int row = rbase + im * 16;
                offA[im] = SWZ((uint32_t)(row * 128 + cA));
            }
            int nbase = warp_n * 32 + (lane & 7) + ((lane >> 4) & 1) * 8;
            int cB = ((lane >> 3) & 1) * 16;
            #pragma unroll
            for (int ig = 0; ig < 2; ig++) {
                int row = nbase + ig * 16;
                offB[ig] = SWZ((uint32_t)(row * 128 + cB));
            }
        }

        int c[D::IM][4][4];
        #pragma unroll
        for (int i = 0; i < D::IM; i++)
            #pragma unroll
            for (int j = 0; j < 4; j++)
                #pragma unroll
                for (int k = 0; k < 4; k++) c[i][j][k] = 0;

        auto load_stage = [&](int s, int kt) {
            uint32_t abase = tiles + s * D::STAGE_SZ;
            uint32_t bbase = abase + D::STAGE_A;
            const int8_t* Ag = A + (size_t)(bm * BM) * K + (size_t)kt * SBK;
            const int8_t* Bg = B + (size_t)(bn * SBN) * K + (size_t)kt * SBK;
            #pragma unroll
            for (int i = 0; i < D::IM; i++) {
                int idx = tid + i * GTHREADS;
                int row = idx >> 3, cc2 = (idx & 7) * 16;
                CP_ASYNC16(abase + SWZ((uint32_t)(row * 128 + cc2)), Ag + (size_t)row * K + cc2);
            }
            #pragma unroll
            for (int i = 0; i < 2; i++) {
                int idx = tid + i * GTHREADS;
                int row = idx >> 3, cc2 = (idx & 7) * 16;
                CP_ASYNC16(bbase + SWZ((uint32_t)(row * 128 + cc2)), Bg + (size_t)row * K + cc2);
            }
        };

        load_stage(0, 0); CP_COMMIT();
        load_stage(1, 1); CP_COMMIT();

        for (int kt = 0; kt < KT; kt++) {
            const int s = kt - (kt / NSTAGE) * NSTAGE;
            CP_WAIT1();
            __syncthreads();

            const uint32_t abase = tiles + s * D::STAGE_SZ;
            const uint32_t bbase = abase + D::STAGE_A;
            #pragma unroll
            for (int kk = 0; kk < SBK; kk += 32) {
                uint32_t a[D::IM][4], b[4][2];
                #pragma unroll
                for (int im = 0; im < D::IM; im++)
                    LDSM_X4(a[im][0], a[im][1], a[im][2], a[im][3], (abase + offA[im]) ^ kk);
                #pragma unroll
                for (int ig = 0; ig < 2; ig++)
                    LDSM_X4(b[2 * ig][0], b[2 * ig][1], b[2 * ig + 1][0], b[2 * ig + 1][1],
                            (bbase + offB[ig]) ^ kk);
                #pragma unroll
                for (int im = 0; im < D::IM; im++)
                    #pragma unroll
                    for (int in = 0; in < 4; in++)
                        mma_s8(c[im][in], a[im], b[in]);
            }

            const int nk = kt + 2;
            if (nk < KT) {
                const int ns = nk - (nk / NSTAGE) * NSTAGE;
                load_stage(ns, nk);
            }
            CP_COMMIT();
        }

        // epilogue (mma)
        #pragma unroll
        for (int in = 0; in < 4; in++) {
            int col = bn * SBN + warp_n * 32 + in * 8 + (lane & 3) * 2;
            int rs0 = rs[col], rs1v = rs[col + 1];
            float b0 = bias[col], b1v = bias[col + 1];
            #pragma unroll
            for (int im = 0; im < D::IM; im++) {
                int row = bm * BM + warp_m * (BM / 4) + im * 16 + (lane >> 2);
                float v0 = (float)(c[im][in][0] - z * rs0) * sc + b0;
                float v1 = (float)(c[im][in][1] - z * rs1v) * sc + b1v;
                float v2 = (float)(c[im][in][2] - z * rs0) * sc + b0;
                float v3 = (float)(c[im][in][3] - z * rs1v) * sc + b1v;
                if (MODE) {
                    v0 = gelu_exact(v0); v1 = gelu_exact(v1);
                    v2 = gelu_exact(v2); v3 = gelu_exact(v3);
                    lmin = fminf(lmin, fminf(fminf(v0, v1), fminf(v2, v3)));
                    lmax = fmaxf(lmax, fmaxf(fmaxf(v0, v1), fmaxf(v2, v3)));
                }
                *(float2*)(out + (size_t)row * N + col) = make_float2(v0, v1);
                *(float2*)(out + (size_t)(row + 8) * N + col) = make_float2(v2, v3);
            }
        }
    } else {
        // ================= dp4a path (spill-free) =================
        uint32_t* sbase = (uint32_t*)(dsmem + (int)(tiles - base0));
        const int wm = wid >> 2, wn = wid & 3;
        const int r0 = wm * (BM / 4) + (lane & 7) * D::RPT;
        const int c0 = wn * 32 + (lane >> 3) * 8;

        auto load_tr = [&](int kt, int s) {
            uint32_t* At = sbase + s * D::SDP;
            uint32_t* Bt = At + BM * 32;
            #pragma unroll
            for (int i = 0; i < D::IM; i++) {
                int idx = tid + i * GTHREADS;
                int r = idx & (BM - 1), c16 = idx >> D::LOGBM;
                uint4 va = *(const uint4*)(A + (size_t)(bm * BM + r) * K + kt * SBK + c16 * 16);
                int k4 = c16 * 4;
                At[(k4 + 0) * BM + r] = va.x; At[(k4 + 1) * BM + r] = va.y;
                At[(k4 + 2) * BM + r] = va.z; At[(k4 + 3) * BM + r] = va.w;
            }
            #pragma unroll
            for (int i = 0; i < 2; i++) {
                int idx = tid + i * GTHREADS;
                int r = idx & 127, c16 = idx >> 7;
                uint4 vb = *(const uint4*)(B + (size_t)(bn * SBN + r) * K + kt * SBK + c16 * 16);
                int k4 = c16 * 4;
                Bt[(k4 + 0) * 128 + r] = vb.x; Bt[(k4 + 1) * 128 + r] = vb.y;
                Bt[(k4 + 2) * 128 + r] = vb.z; Bt[(k4 + 3) * 128 + r] = vb.w;
            }
        };

        int acc[D::RPT][8];
        #pragma unroll
        for (int i = 0; i < D::RPT; i++)
            #pragma unroll
            for (int j = 0; j < 8; j++) acc[i][j] = 0;

        load_tr(0, 0);
        __syncthreads();

        for (int kt = 0; kt < KT; kt++) {
            const uint32_t* At = sbase + (kt & 1) * D::SDP;
            const uint32_t* Bt = At + BM * 32;
            #pragma unroll 8
            for (int k4 = 0; k4 < 32; k4++) {
                int a[D::RPT];
                if constexpr (BM == 128) {
                    uint4 a4 = *(const uint4*)(At + k4 * BM + r0);
                    a[0] = (int)a4.x; a[1] = (int)a4.y; a[2] = (int)a4.z; a[3] = (int)a4.w;
                } else {
                    uint2 a2 = *(const uint2*)(At + k4 * BM + r0);
                    a[0] = (int)a2.x; a[1] = (int)a2.y;
                }
                uint4 b4 = *(const uint4*)(Bt + k4 * 128 + c0);
                uint4 b5 = *(const uint4*)(Bt + k4 * 128 + c0 + 4);
                int b[8] = {(int)b4.x, (int)b4.y, (int)b4.z, (int)b4.w,
                            (int)b5.x, (int)b5.y, (int)b5.z, (int)b5.w};
                #pragma unroll
                for (int i = 0; i < D::RPT; i++)
                    #pragma unroll
                    for (int j = 0; j < 8; j++)
                        acc[i][j] = dp4a(a[i], b[j], acc[i][j]);
            }
            if (kt + 1 < KT) load_tr(kt + 1, (kt + 1) & 1);
            __syncthreads();
        }

        // epilogue (dp4a)
        const int col0 = bn * SBN + c0;
        int zr[8]; float bb[8];
        #pragma unroll
        for (int j = 0; j < 8; j++) { zr[j] = z * rs[col0 + j]; bb[j] = bias[col0 + j]; }
        #pragma unroll
        for (int i = 0; i < D::RPT; i++) {
            size_t ro = (size_t)(bm * BM + r0 + i) * N + col0;
            float v[8];
            #pragma unroll
            for (int j = 0; j < 8; j++) {
                float f = (float)(acc[i][j] - zr[j]) * sc + bb[j];
                if (MODE) {
                    f = gelu_exact(f);
                    lmin = fminf(lmin, f);
                    lmax = fmaxf(lmax, f);
                }
                v[j] = f;
            }
            *(float4*)(out + ro)     = make_float4(v[0], v[1], v[2], v[3]);
            *(float4*)(out + ro + 4) = make_float4(v[4], v[5], v[6], v[7]);
        }
    }

    // ---- common min/max reduction (MODE 1) ----
    if (MODE) {
        #pragma unroll
        for (int o = 16; o; o >>= 1) {
            lmin = fminf(lmin, __shfl_xor_sync(0xffffffffu, lmin, o));
            lmax = fmaxf(lmax, __shfl_xor_sync(0xffffffffu, lmax, o));
        }
        __shared__ float red[2][16];
        if (lane == 0) { red[0][wid] = lmin; red[1][wid] = lmax; }
        __syncthreads();
        if (tid == 0) {
            float m = red[0][0], Mx = red[1][0];
            #pragma unroll
            for (int w = 1; w < 16; w++) { m = fminf(m, red[0][w]); Mx = fmaxf(Mx, red[1][w]); }
            atomicMin(&g_stats[4], fenc(m));
            atomicMax(&g_stats[5], fenc(Mx));
        }
    }
}

// ---------------- launch ----------------
extern "C" void kernel_launch(void* const* d_in, const int* in_sizes, int n_in,
                              void* d_out, int out_size) {
    const float* x  = (const float*)d_in[0];
    const float* W1 = (const float*)d_in[1];
    const float* b1 = (const float*)d_in[2];
    const float* W2 = (const float*)d_in[3];
    const float* b2 = (const float*)d_in[4];
    float* out = (float*)d_out;

    const size_t nx = (size_t)M_DIM * D_DIM;
    const size_t nh = (size_t)M_DIM * H_DIM;

    cudaFuncSetAttribute(k_gemm<1, 128>, cudaFuncAttributeMaxDynamicSharedMemorySize,
                         GemmDims<128>::SMEM_DYN);
    cudaFuncSetAttribute(k_gemm<0, 64>, cudaFuncAttributeMaxDynamicSharedMemorySize,
                         GemmDims<64>::SMEM_DYN);

    k_init<<<1, 32>>>();

    k_stats<<<STAT_BX + 2 * STAT_BW, 256>>>(
        (const float4*)x, (int)(nx / 4),
        (const float4*)W1, (int)((size_t)H_DIM * D_DIM / 4),
        (const float4*)W2, (int)((size_t)D_DIM * H_DIM / 4));
    k_fin1<<<1, 32>>>();

    k_quant_all<<<QA_BX + H_DIM + D_DIM, 256>>>((const float4*)x, W1, W2);

    // GEMM1: 128x128 tiles -> gelu -> g_h (fp32) + h min/max; 50/50 hybrid
    dim3 g1(H_DIM / SBN, M_DIM / 128);   // (32, 128)
    k_gemm<1, 128><<<g1, GTHREADS, GemmDims<128>::SMEM_DYN>>>(b1, H_DIM, D_DIM, nullptr);

    k_fin2<<<1, 32>>>();
    k_quant_h<<<8192, 256>>>(nh / 4);

    // GEMM2: 64x128 tiles (wave-quantization fix, R12); 50/50 hybrid
    dim3 g2(D_DIM / SBN, M_DIM / 64);    // (8, 256)
    k_gemm<0, 64><<<g2, GTHREADS, GemmDims<64>::SMEM_DYN>>>(b2, D_DIM, H_DIM, out);
}

// round 15
// speedup vs baseline: 1.0476x; 1.0476x over previous
#include <cuda_runtime.h>
#include <cstdint>

// ---------------- problem dimensions (fixed by the dataset) ----------------
#define M_DIM 16384   // 4 * 4096 tokens
#define D_DIM 1024
#define H_DIM 4096

// NOTE (env, R2): harness PTX target is sm_103 (no 'a') -> no tcgen05/TMEM.
// NOTE (R5): h must stay fp32 (fp16 h -> rel_err 1.9e-3 FAIL).
// NOTE (R10): forced mma+dp4a co-residency REGRESSED; mod-8 same-kind pairing
//   is required for the hybrid win.
// NOTE (R14): split-response measured: f_dp4a 0 -> ~1980, 0.375 -> 1883,
//   0.5 -> 1948. dp4a ~ 0.75x mma rate; quadratic fit minimum ~ f=0.27.
// THIS ROUND: R12 verbatim, ONE token: kind threshold 5 -> 6
//   (mma 75% / dp4a 25%), interpolating toward the fitted optimum.

// ---------------- device scratch (static, allocation-free) ----------------
__device__ __align__(128) int8_t  g_xq[(size_t)M_DIM * D_DIM];     // 16 MB
__device__ __align__(128) int8_t  g_hq[(size_t)M_DIM * H_DIM];     // 64 MB
__device__ __align__(128) float   g_h [(size_t)M_DIM * H_DIM];     // 256 MB
__device__ __align__(128) int8_t  g_w1q[(size_t)H_DIM * D_DIM];    // 4 MB
__device__ __align__(128) int8_t  g_w2q[(size_t)D_DIM * H_DIM];    // 4 MB
__device__ int     g_rs1[H_DIM];
__device__ int     g_rs2[D_DIM];
// stats: 0=min_x(enc) 1=max_x(enc) 2=absmax_w1 3=absmax_w2 4=min_h(enc) 5=max_h(enc)
__device__ unsigned g_stats[6];
// scales: 0=sx 1=sw1 2=sw2 3=s1(sx*sw1) 4=sh 5=s2(sh*sw2)
__device__ float    g_scale[6];
__device__ int      g_zp[2];   // 0=zx 1=zh

// ---------------- helpers ----------------
__device__ __forceinline__ unsigned fenc(float f) {
    unsigned u = __float_as_uint(f);
    return (u & 0x80000000u) ? ~u : (u | 0x80000000u);
}
__device__ __forceinline__ float fdec(unsigned e) {
    return __uint_as_float((e & 0x80000000u) ? (e ^ 0x80000000u) : ~e);
}
__device__ __forceinline__ float gelu_exact(float v) {
    return 0.5f * v * (1.0f + erff(v * 0.7071067811865476f));
}
__device__ __forceinline__ uint32_t smem_u32(const void* p) {
    uint32_t a;
    asm("{ .reg .u64 t; cvta.to.shared.u64 t, %1; cvt.u32.u64 %0, t; }" : "=r"(a) : "l"(p));
    return a;
}
__device__ __forceinline__ int dp4a(int a, int b, int c) {
    int d;
    asm("dp4a.s32.s32 %0, %1, %2, %3;" : "=r"(d) : "r"(a), "r"(b), "r"(c));
    return d;
}

#define CP_ASYNC16(dst_u32, src_ptr) \
    asm volatile("cp.async.cg.shared.global [%0], [%1], 16;\n" :: "r"(dst_u32), "l"(src_ptr))
#define CP_COMMIT() asm volatile("cp.async.commit_group;\n" ::: "memory")
#define CP_WAIT1()  asm volatile("cp.async.wait_group 1;\n" ::: "memory")

#define SWZ(off) ((off) ^ (((off) >> 3) & 0x70))

#define LDSM_X4(r0, r1, r2, r3, addr) \
    asm volatile("ldmatrix.sync.aligned.m8n8.x4.shared.b16 {%0,%1,%2,%3}, [%4];" \
                 : "=r"(r0), "=r"(r1), "=r"(r2), "=r"(r3) : "r"(addr))

__device__ __forceinline__ void mma_s8(int* c, const uint32_t* a, const uint32_t* b) {
    asm volatile(
        "mma.sync.aligned.m16n8k32.row.col.s32.s8.s8.s32 "
        "{%0,%1,%2,%3}, {%4,%5,%6,%7}, {%8,%9}, {%0,%1,%2,%3};\n"
        : "+r"(c[0]), "+r"(c[1]), "+r"(c[2]), "+r"(c[3])
        : "r"(a[0]), "r"(a[1]), "r"(a[2]), "r"(a[3]), "r"(b[0]), "r"(b[1]));
}

// ---------------- init ----------------
__global__ void k_init() {
    if (threadIdx.x == 0) {
        g_stats[0] = 0xFFFFFFFFu; g_stats[1] = 0u;
        g_stats[2] = 0u;          g_stats[3] = 0u;
        g_stats[4] = 0xFFFFFFFFu; g_stats[5] = 0u;
    }
}

// ---------------- fused stats: minmax(x) || absmax(W1) || absmax(W2) ----------------
static constexpr int STAT_BX = 4096;
static constexpr int STAT_BW = 1024;

__global__ void k_stats(const float4* __restrict__ x, int nx4,
                        const float4* __restrict__ w1, int n14,
                        const float4* __restrict__ w2, int n24) {
    const int b = blockIdx.x;
    __shared__ float sm[2][8];
    if (b < STAT_BX) {
        float lmin = 3.4e38f, lmax = -3.4e38f;
        for (int i = b * blockDim.x + threadIdx.x; i < nx4; i += STAT_BX * blockDim.x) {
            float4 v = x[i];
            lmin = fminf(lmin, fminf(fminf(v.x, v.y), fminf(v.z, v.w)));
            lmax = fmaxf(lmax, fmaxf(fmaxf(v.x, v.y), fmaxf(v.z, v.w)));
        }
        #pragma unroll
        for (int o = 16; o; o >>= 1) {
            lmin = fminf(lmin, __shfl_xor_sync(0xffffffffu, lmin, o));
            lmax = fmaxf(lmax, __shfl_xor_sync(0xffffffffu, lmax, o));
        }
        if ((threadIdx.x & 31) == 0) { sm[0][threadIdx.x >> 5] = lmin; sm[1][threadIdx.x >> 5] = lmax; }
        __syncthreads();
        if (threadIdx.x == 0) {
            float m = sm[0][0], M = sm[1][0];
            #pragma unroll
            for (int w = 1; w < 8; w++) { m = fminf(m, sm[0][w]); M = fmaxf(M, sm[1][w]); }
            atomicMin(&g_stats[0], fenc(m));
            atomicMax(&g_stats[1], fenc(M));
        }
    } else {
        const int which = (b < STAT_BX + STAT_BW) ? 0 : 1;
        const int b0 = which ? (STAT_BX + STAT_BW) : STAT_BX;
        const float4* w = which ? w2 : w1;
        const int n4 = which ? n24 : n14;
        const int slot = which ? 3 : 2;
        float lmax = 0.0f;
        for (int i = (b - b0) * blockDim.x + threadIdx.x; i < n4; i += STAT_BW * blockDim.x) {
            float4 v = w[i];
            lmax = fmaxf(lmax, fmaxf(fmaxf(fabsf(v.x), fabsf(v.y)), fmaxf(fabsf(v.z), fabsf(v.w))));
        }
        #pragma unroll
        for (int o = 16; o; o >>= 1) lmax = fmaxf(lmax, __shfl_xor_sync(0xffffffffu, lmax, o));
        if ((threadIdx.x & 31) == 0) sm[0][threadIdx.x >> 5] = lmax;
        __syncthreads();
        if (threadIdx.x == 0) {
            float M = sm[0][0];
            #pragma unroll
            for (int w2i = 1; w2i < 8; w2i++) M = fmaxf(M, sm[0][w2i]);
            atomicMax(&g_stats[slot], __float_as_uint(M));
        }
    }
}

// ---------------- finalize input/weight scales ----------------
__global__ void k_fin1() {
    if (threadIdx.x != 0) return;
    float an = fdec(g_stats[0]), ax = fdec(g_stats[1]);
    float sx = fmaxf(__fdiv_rn(ax - an, 255.0f), 1e-8f);
    float zxf = rintf(__fdiv_rn(-an, sx)) - 128.0f;
    zxf = fminf(fmaxf(zxf, -128.0f), 127.0f);
    float sw1 = fmaxf(__fdiv_rn(__uint_as_float(g_stats[2]), 127.0f), 1e-8f);
    float sw2 = fmaxf(__fdiv_rn(__uint_as_float(g_stats[3]), 127.0f), 1e-8f);
    g_scale[0] = sx; g_scale[1] = sw1; g_scale[2] = sw2;
    g_scale[3] = sx * sw1;
    g_zp[0] = (int)zxf;
}

// ---------------- finalize h scales (after GEMM1) ----------------
__global__ void k_fin2() {
    if (threadIdx.x != 0) return;
    float hn = fdec(g_stats[4]), hx = fdec(g_stats[5]);
    float sh = fmaxf(__fdiv_rn(hx - hn, 255.0f), 1e-8f);
    float zhf = rintf(__fdiv_rn(-hn, sh)) - 128.0f;
    zhf = fminf(fmaxf(zhf, -128.0f), 127.0f);
    g_scale[4] = sh;
    g_scale[5] = sh * g_scale[2];
    g_zp[1] = (int)zhf;
}

// ---------------- fused quantize: x || W1(+rs1) || W2(+rs2) ----------------
static constexpr int QA_BX = 2048;

__global__ void k_quant_all(const float4* __restrict__ x,
                            const float* __restrict__ W1,
                            const float* __restrict__ W2) {
    const int b = blockIdx.x;
    if (b < QA_BX) {
        const size_t n4 = (size_t)M_DIM * D_DIM / 4;
        char4* dst = (char4*)g_xq;
        float s = g_scale[0];
        float zp = (float)g_zp[0];
        for (size_t i = b * (size_t)blockDim.x + threadIdx.x; i < n4;
             i += (size_t)QA_BX * blockDim.x) {
            float4 v = x[i];
            float q0 = fminf(fmaxf(rintf(__fdiv_rn(v.x, s)) + zp, -128.0f), 127.0f);
            float q1 = fminf(fmaxf(rintf(__fdiv_rn(v.y, s)) + zp, -128.0f), 127.0f);
            float q2 = fminf(fmaxf(rintf(__fdiv_rn(v.z, s)) + zp, -128.0f), 127.0f);
            float q3 = fminf(fmaxf(rintf(__fdiv_rn(v.w, s)) + zp, -128.0f), 127.0f);
            char4 c; c.x = (char)(int)q0; c.y = (char)(int)q1; c.z = (char)(int)q2; c.w = (char)(int)q3;
            dst[i] = c;
        }
    } else {
        const int which = (b < QA_BX + H_DIM) ? 0 : 1;
        const int row = which ? (b - QA_BX - H_DIM) : (b - QA_BX);
        const int cols = which ? H_DIM : D_DIM;
        const float* W = which ? W2 : W1;
        int8_t* wq = which ? g_w2q : g_w1q;
        int* rs = which ? g_rs2 : g_rs1;
        float sw = which ? g_scale[2] : g_scale[1];
        const float4* src = (const float4*)(W + (size_t)row * cols);
        char4* dst = (char4*)(wq + (size_t)row * cols);
        int acc = 0;
        for (int c = threadIdx.x; c < (cols >> 2); c += blockDim.x) {
            float4 v = src[c];
            float q0 = fminf(fmaxf(rintf(__fdiv_rn(v.x, sw)), -127.0f), 127.0f);
            float q1 = fminf(fmaxf(rintf(__fdiv_rn(v.y, sw)), -127.0f), 127.0f);
            float q2 = fminf(fmaxf(rintf(__fdiv_rn(v.z, sw)), -127.0f), 127.0f);
            float q3 = fminf(fmaxf(rintf(__fdiv_rn(v.w, sw)), -127.0f), 127.0f);
            int i0 = (int)q0, i1 = (int)q1, i2 = (int)q2, i3 = (int)q3;
            acc += i0 + i1 + i2 + i3;
            char4 cc; cc.x = (char)i0; cc.y = (char)i1; cc.z = (char)i2; cc.w = (char)i3;
            dst[c] = cc;
        }
        #pragma unroll
        for (int o = 16; o; o >>= 1) acc += __shfl_xor_sync(0xffffffffu, acc, o);
        __shared__ int sm[8];
        if ((threadIdx.x & 31) == 0) sm[threadIdx.x >> 5] = acc;
        __syncthreads();
        if (threadIdx.x == 0) {
            int t = 0;
            #pragma unroll
            for (int w = 0; w < 8; w++) t += sm[w];
            rs[row] = t;
        }
    }
}

// ---------------- h quantize (fp32 -> int8) ----------------
__global__ void k_quant_h(size_t n4) {
    const float4* src = (const float4*)g_h;
    char4* dst = (char4*)g_hq;
    float s = g_scale[4];
    float zp = (float)g_zp[1];
    for (size_t i = blockIdx.x * (size_t)blockDim.x + threadIdx.x; i < n4;
         i += (size_t)gridDim.x * blockDim.x) {
        float4 v = src[i];
        float q0 = fminf(fmaxf(rintf(__fdiv_rn(v.x, s)) + zp, -128.0f), 127.0f);
        float q1 = fminf(fmaxf(rintf(__fdiv_rn(v.y, s)) + zp, -128.0f), 127.0f);
        float q2 = fminf(fmaxf(rintf(__fdiv_rn(v.z, s)) + zp, -128.0f), 127.0f);
        float q3 = fminf(fmaxf(rintf(__fdiv_rn(v.w, s)) + zp, -128.0f), 127.0f);
        char4 c; c.x = (char)(int)q0; c.y = (char)(int)q1; c.z = (char)(int)q2; c.w = (char)(int)q3;
        dst[i] = c;
    }
}

// ========== hybrid int8 GEMM, templated M-tile (BM in {128, 64}) ==========
// kind 0 (mma):  16 warps, warp tile (BM/4)x32, 3-stage cp.async
// kind 1 (dp4a): BMx128 tile, K-transposed smem, 2-stage, spill-free
// kind = ((bn+bm)&7)<6 : mma 75% / dp4a 25% (fitted optimum ~f_d=0.27).
//   Mod-8 keeps co-resident pairs same kind (delta 24 = 0 mod 8), per R10.
static constexpr int SBN = 128;
static constexpr int SBK = 128;
static constexpr int NSTAGE = 3;
static constexpr int GTHREADS = 512;

template <int BM> struct GemmDims {
    static constexpr int IM = BM / 64;
    static constexpr int RPT = BM / 32;
    static constexpr int LOGBM = (BM == 128) ? 7 : 6;
    static constexpr int STAGE_A = BM * SBK;
    static constexpr int STAGE_SZ = STAGE_A + SBN * SBK;
    static constexpr int SMEM_DYN = 1024 + NSTAGE * STAGE_SZ;
    static constexpr int SDP = BM * 32 + 4096;
};

template <int MODE, int BM>
__global__ __launch_bounds__(GTHREADS, 2)
void k_gemm(const float* __restrict__ bias, int N, int K, float* __restrict__ outp) {
    using D = GemmDims<BM>;
    extern __shared__ char dsmem[];
    const int tid = threadIdx.x, wid = tid >> 5, lane = tid & 31;
    const int bm = blockIdx.y, bn = blockIdx.x;

    const int8_t* __restrict__ A = MODE ? g_xq : g_hq;
    const int8_t* __restrict__ B = MODE ? g_w1q : g_w2q;
    const int* __restrict__ rs   = MODE ? g_rs1 : g_rs2;
    float* __restrict__ out      = MODE ? g_h : outp;
    const float sc = MODE ? g_scale[3] : g_scale[5];
    const int   z  = MODE ? g_zp[0] : g_zp[1];

    const uint32_t base0 = smem_u32(dsmem);
    const uint32_t tiles = (base0 + 1023) & ~1023u;
    const int KT = K >> 7;

    const int kind = (((bn + bm) & 7) < 6) ? 0 : 1;

    float lmin = 3.4e38f, lmax = -3.4e38f;

    if (kind == 0) {
        // ================= mma path =================
        const int warp_m = wid & 3;
        const int warp_n = wid >> 2;

        uint32_t offA[D::IM], offB[2];
        {
            int rbase = warp_m * (BM / 4) + (lane & 7) + ((lane >> 3) & 1) * 8;
            int cA = ((lane >> 4) & 1) * 16;
            #pragma unroll
            for (int im = 0; im < D::IM; im++) {
                int row = rbase + im * 16;
                offA[im] = SWZ((uint32_t)(row * 128 + cA));
            }
            int nbase = warp_n * 32 + (lane & 7) + ((lane >> 4) & 1) * 8;
            int cB = ((lane >> 3) & 1) * 16;
            #pragma unroll
            for (int ig = 0; ig < 2; ig++) {
                int row = nbase + ig * 16;
                offB[ig] = SWZ((uint32_t)(row * 128 + cB));
            }
        }

        int c[D::IM][4][4];
        #pragma unroll
        for (int i = 0; i < D::IM; i++)
            #pragma unroll
            for (int j = 0; j < 4; j++)
                #pragma unroll
                for (int k = 0; k < 4; k++) c[i][j][k] = 0;

        auto load_stage = [&](int s, int kt) {
            uint32_t abase = tiles + s * D::STAGE_SZ;
            uint32_t bbase = abase + D::STAGE_A;
            const int8_t* Ag = A + (size_t)(bm * BM) * K + (size_t)kt * SBK;
            const int8_t* Bg = B + (size_t)(bn * SBN) * K + (size_t)kt * SBK;
            #pragma unroll
            for (int i = 0; i < D::IM; i++) {
                int idx = tid + i * GTHREADS;
                int row = idx >> 3, cc2 = (idx & 7) * 16;
                CP_ASYNC16(abase + SWZ((uint32_t)(row * 128 + cc2)), Ag + (size_t)row * K + cc2);
            }
            #pragma unroll
            for (int i = 0; i < 2; i++) {
                int idx = tid + i * GTHREADS;
                int row = idx >> 3, cc2 = (idx & 7) * 16;
                CP_ASYNC16(bbase + SWZ((uint32_t)(row * 128 + cc2)), Bg + (size_t)row * K + cc2);
            }
        };

        load_stage(0, 0); CP_COMMIT();
        load_stage(1, 1); CP_COMMIT();

        for (int kt = 0; kt < KT; kt++) {
            const int s = kt - (kt / NSTAGE) * NSTAGE;
            CP_WAIT1();
            __syncthreads();

            const uint32_t abase = tiles + s * D::STAGE_SZ;
            const uint32_t bbase = abase + D::STAGE_A;
            #pragma unroll
            for (int kk = 0; kk < SBK; kk += 32) {
                uint32_t a[D::IM][4], b[4][2];
                #pragma unroll
                for (int im = 0; im < D::IM; im++)
                    LDSM_X4(a[im][0], a[im][1], a[im][2], a[im][3], (abase + offA[im]) ^ kk);
                #pragma unroll
                for (int ig = 0; ig < 2; ig++)
                    LDSM_X4(b[2 * ig][0], b[2 * ig][1], b[2 * ig + 1][0], b[2 * ig + 1][1],
                            (bbase + offB[ig]) ^ kk);
                #pragma unroll
                for (int im = 0; im < D::IM; im++)
                    #pragma unroll
                    for (int in = 0; in < 4; in++)
                        mma_s8(c[im][in], a[im], b[in]);
            }

            const int nk = kt + 2;
            if (nk < KT) {
                const int ns = nk - (nk / NSTAGE) * NSTAGE;
                load_stage(ns, nk);
            }
            CP_COMMIT();
        }

        // epilogue (mma)
        #pragma unroll
        for (int in = 0; in < 4; in++) {
            int col = bn * SBN + warp_n * 32 + in * 8 + (lane & 3) * 2;
            int rs0 = rs[col], rs1v = rs[col + 1];
            float b0 = bias[col], b1v = bias[col + 1];
            #pragma unroll
            for (int im = 0; im < D::IM; im++) {
                int row = bm * BM + warp_m * (BM / 4) + im * 16 + (lane >> 2);
                float v0 = (float)(c[im][in][0] - z * rs0) * sc + b0;
                float v1 = (float)(c[im][in][1] - z * rs1v) * sc + b1v;
                float v2 = (float)(c[im][in][2] - z * rs0) * sc + b0;
                float v3 = (float)(c[im][in][3] - z * rs1v) * sc + b1v;
                if (MODE) {
                    v0 = gelu_exact(v0); v1 = gelu_exact(v1);
                    v2 = gelu_exact(v2); v3 = gelu_exact(v3);
                    lmin = fminf(lmin, fminf(fminf(v0, v1), fminf(v2, v3)));
                    lmax = fmaxf(lmax, fmaxf(fmaxf(v0, v1), fmaxf(v2, v3)));
                }
                *(float2*)(out + (size_t)row * N + col) = make_float2(v0, v1);
                *(float2*)(out + (size_t)(row + 8) * N + col) = make_float2(v2, v3);
            }
        }
    } else {
        // ================= dp4a path (spill-free) =================
        uint32_t* sbase = (uint32_t*)(dsmem + (int)(tiles - base0));
        const int wm = wid >> 2, wn = wid & 3;
        const int r0 = wm * (BM / 4) + (lane & 7) * D::RPT;
        const int c0 = wn * 32 + (lane >> 3) * 8;

        auto load_tr = [&](int kt, int s) {
            uint32_t* At = sbase + s * D::SDP;
            uint32_t* Bt = At + BM * 32;
            #pragma unroll
            for (int i = 0; i < D::IM; i++) {
                int idx = tid + i * GTHREADS;
                int r = idx & (BM - 1), c16 = idx >> D::LOGBM;
                uint4 va = *(const uint4*)(A + (size_t)(bm * BM + r) * K + kt * SBK + c16 * 16);
                int k4 = c16 * 4;
                At[(k4 + 0) * BM + r] = va.x; At[(k4 + 1) * BM + r] = va.y;
                At[(k4 + 2) * BM + r] = va.z; At[(k4 + 3) * BM + r] = va.w;
            }
            #pragma unroll
            for (int i = 0; i < 2; i++) {
                int idx = tid + i * GTHREADS;
                int r = idx & 127, c16 = idx >> 7;
                uint4 vb = *(const uint4*)(B + (size_t)(bn * SBN + r) * K + kt * SBK + c16 * 16);
                int k4 = c16 * 4;
                Bt[(k4 + 0) * 128 + r] = vb.x; Bt[(k4 + 1) * 128 + r] = vb.y;
                Bt[(k4 + 2) * 128 + r] = vb.z; Bt[(k4 + 3) * 128 + r] = vb.w;
            }
        };

        int acc[D::RPT][8];
        #pragma unroll
        for (int i = 0; i < D::RPT; i++)
            #pragma unroll
            for (int j = 0; j < 8; j++) acc[i][j] = 0;

        load_tr(0, 0);
        __syncthreads();

        for (int kt = 0; kt < KT; kt++) {
            const uint32_t* At = sbase + (kt & 1) * D::SDP;
            const uint32_t* Bt = At + BM * 32;
            #pragma unroll 8
            for (int k4 = 0; k4 < 32; k4++) {
                int a[D::RPT];
                if constexpr (BM == 128) {
                    uint4 a4 = *(const uint4*)(At + k4 * BM + r0);
                    a[0] = (int)a4.x; a[1] = (int)a4.y; a[2] = (int)a4.z; a[3] = (int)a4.w;
                } else {
                    uint2 a2 = *(const uint2*)(At + k4 * BM + r0);
                    a[0] = (int)a2.x; a[1] = (int)a2.y;
                }
                uint4 b4 = *(const uint4*)(Bt + k4 * 128 + c0);
                uint4 b5 = *(const uint4*)(Bt + k4 * 128 + c0 + 4);
                int b[8] = {(int)b4.x, (int)b4.y, (int)b4.z, (int)b4.w,
                            (int)b5.x, (int)b5.y, (int)b5.z, (int)b5.w};
                #pragma unroll
                for (int i = 0; i < D::RPT; i++)
                    #pragma unroll
                    for (int j = 0; j < 8; j++)
                        acc[i][j] = dp4a(a[i], b[j], acc[i][j]);
            }
            if (kt + 1 < KT) load_tr(kt + 1, (kt + 1) & 1);
            __syncthreads();
        }

        // epilogue (dp4a)
        const int col0 = bn * SBN + c0;
        int zr[8]; float bb[8];
        #pragma unroll
        for (int j = 0; j < 8; j++) { zr[j] = z * rs[col0 + j]; bb[j] = bias[col0 + j]; }
        #pragma unroll
        for (int i = 0; i < D::RPT; i++) {
            size_t ro = (size_t)(bm * BM + r0 + i) * N + col0;
            float v[8];
            #pragma unroll
            for (int j = 0; j < 8; j++) {
                float f = (float)(acc[i][j] - zr[j]) * sc + bb[j];
                if (MODE) {
                    f = gelu_exact(f);
                    lmin = fminf(lmin, f);
                    lmax = fmaxf(lmax, f);
                }
                v[j] = f;
            }
            *(float4*)(out + ro)     = make_float4(v[0], v[1], v[2], v[3]);
            *(float4*)(out + ro + 4) = make_float4(v[4], v[5], v[6], v[7]);
        }
    }

    // ---- common min/max reduction (MODE 1) ----
    if (MODE) {
        #pragma unroll
        for (int o = 16; o; o >>= 1) {
            lmin = fminf(lmin, __shfl_xor_sync(0xffffffffu, lmin, o));
            lmax = fmaxf(lmax, __shfl_xor_sync(0xffffffffu, lmax, o));
        }
        __shared__ float red[2][16];
        if (lane == 0) { red[0][wid] = lmin; red[1][wid] = lmax; }
        __syncthreads();
        if (tid == 0) {
            float m = red[0][0], Mx = red[1][0];
            #pragma unroll
            for (int w = 1; w < 16; w++) { m = fminf(m, red[0][w]); Mx = fmaxf(Mx, red[1][w]); }
            atomicMin(&g_stats[4], fenc(m));
            atomicMax(&g_stats[5], fenc(Mx));
        }
    }
}

// ---------------- launch ----------------
extern "C" void kernel_launch(void* const* d_in, const int* in_sizes, int n_in,
                              void* d_out, int out_size) {
    const float* x  = (const float*)d_in[0];
    const float* W1 = (const float*)d_in[1];
    const float* b1 = (const float*)d_in[2];
    const float* W2 = (const float*)d_in[3];
    const float* b2 = (const float*)d_in[4];
    float* out = (float*)d_out;

    const size_t nx = (size_t)M_DIM * D_DIM;
    const size_t nh = (size_t)M_DIM * H_DIM;

    cudaFuncSetAttribute(k_gemm<1, 128>, cudaFuncAttributeMaxDynamicSharedMemorySize,
                         GemmDims<128>::SMEM_DYN);
    cudaFuncSetAttribute(k_gemm<0, 64>, cudaFuncAttributeMaxDynamicSharedMemorySize,
                         GemmDims<64>::SMEM_DYN);

    k_init<<<1, 32>>>();

    k_stats<<<STAT_BX + 2 * STAT_BW, 256>>>(
        (const float4*)x, (int)(nx / 4),
        (const float4*)W1, (int)((size_t)H_DIM * D_DIM / 4),
        (const float4*)W2, (int)((size_t)D_DIM * H_DIM / 4));
    k_fin1<<<1, 32>>>();

    k_quant_all<<<QA_BX + H_DIM + D_DIM, 256>>>((const float4*)x, W1, W2);

    // GEMM1: 128x128 tiles -> gelu -> g_h (fp32) + h min/max; 75/25 hybrid
    dim3 g1(H_DIM / SBN, M_DIM / 128);   // (32, 128)
    k_gemm<1, 128><<<g1, GTHREADS, GemmDims<128>::SMEM_DYN>>>(b1, H_DIM, D_DIM, nullptr);

    k_fin2<<<1, 32>>>();
    k_quant_h<<<8192, 256>>>(nh / 4);

    // GEMM2: 64x128 tiles (wave-quantization fix, R12); 75/25 hybrid
    dim3 g2(D_DIM / SBN, M_DIM / 64);    // (8, 256)
    k_gemm<0, 64><<<g2, GTHREADS, GemmDims<64>::SMEM_DYN>>>(b2, D_DIM, H_DIM, out);
}

// round 16
// speedup vs baseline: 1.0585x; 1.0104x over previous
#include <cuda_runtime.h>
#include <cstdint>

// ---------------- problem dimensions (fixed by the dataset) ----------------
#define M_DIM 16384   // 4 * 4096 tokens
#define D_DIM 1024
#define H_DIM 4096

// NOTE (env, R2): harness PTX target is sm_103 (no 'a') -> no tcgen05/TMEM.
// NOTE (R5): h must stay fp32 (fp16 h -> rel_err 1.9e-3 FAIL).
// NOTE (R10): forced mma+dp4a co-residency REGRESSED; mod-8 same-kind pairing required.
// NOTE (R15): split-response optimum found: kind=((bn+bm)&7)<6 (75% mma / 25%
//   dp4a) -> 1859.6us. Split tuning closed (mod-8 granularity exhausted).
// THIS ROUND: k_quant_h only - static schedule, 16 float4/thread, 4 unrolled
//   batches of 4 independent strided loads (MLP=4) to unhide DRAM latency.

// ---------------- device scratch (static, allocation-free) ----------------
__device__ __align__(128) int8_t  g_xq[(size_t)M_DIM * D_DIM];     // 16 MB
__device__ __align__(128) int8_t  g_hq[(size_t)M_DIM * H_DIM];     // 64 MB
__device__ __align__(128) float   g_h [(size_t)M_DIM * H_DIM];     // 256 MB
__device__ __align__(128) int8_t  g_w1q[(size_t)H_DIM * D_DIM];    // 4 MB
__device__ __align__(128) int8_t  g_w2q[(size_t)D_DIM * H_DIM];    // 4 MB
__device__ int     g_rs1[H_DIM];
__device__ int     g_rs2[D_DIM];
// stats: 0=min_x(enc) 1=max_x(enc) 2=absmax_w1 3=absmax_w2 4=min_h(enc) 5=max_h(enc)
__device__ unsigned g_stats[6];
// scales: 0=sx 1=sw1 2=sw2 3=s1(sx*sw1) 4=sh 5=s2(sh*sw2)
__device__ float    g_scale[6];
__device__ int      g_zp[2];   // 0=zx 1=zh

// ---------------- helpers ----------------
__device__ __forceinline__ unsigned fenc(float f) {
    unsigned u = __float_as_uint(f);
    return (u & 0x80000000u) ? ~u : (u | 0x80000000u);
}
__device__ __forceinline__ float fdec(unsigned e) {
    return __uint_as_float((e & 0x80000000u) ? (e ^ 0x80000000u) : ~e);
}
__device__ __forceinline__ float gelu_exact(float v) {
    return 0.5f * v * (1.0f + erff(v * 0.7071067811865476f));
}
__device__ __forceinline__ uint32_t smem_u32(const void* p) {
    uint32_t a;
    asm("{ .reg .u64 t; cvta.to.shared.u64 t, %1; cvt.u32.u64 %0, t; }" : "=r"(a) : "l"(p));
    return a;
}
__device__ __forceinline__ int dp4a(int a, int b, int c) {
    int d;
    asm("dp4a.s32.s32 %0, %1, %2, %3;" : "=r"(d) : "r"(a), "r"(b), "r"(c));
    return d;
}

#define CP_ASYNC16(dst_u32, src_ptr) \
    asm volatile("cp.async.cg.shared.global [%0], [%1], 16;\n" :: "r"(dst_u32), "l"(src_ptr))
#define CP_COMMIT() asm volatile("cp.async.commit_group;\n" ::: "memory")
#define CP_WAIT1()  asm volatile("cp.async.wait_group 1;\n" ::: "memory")

#define SWZ(off) ((off) ^ (((off) >> 3) & 0x70))

#define LDSM_X4(r0, r1, r2, r3, addr) \
    asm volatile("ldmatrix.sync.aligned.m8n8.x4.shared.b16 {%0,%1,%2,%3}, [%4];" \
                 : "=r"(r0), "=r"(r1), "=r"(r2), "=r"(r3) : "r"(addr))

__device__ __forceinline__ void mma_s8(int* c, const uint32_t* a, const uint32_t* b) {
    asm volatile(
        "mma.sync.aligned.m16n8k32.row.col.s32.s8.s8.s32 "
        "{%0,%1,%2,%3}, {%4,%5,%6,%7}, {%8,%9}, {%0,%1,%2,%3};\n"
        : "+r"(c[0]), "+r"(c[1]), "+r"(c[2]), "+r"(c[3])
        : "r"(a[0]), "r"(a[1]), "r"(a[2]), "r"(a[3]), "r"(b[0]), "r"(b[1]));
}

// ---------------- init ----------------
__global__ void k_init() {
    if (threadIdx.x == 0) {
        g_stats[0] = 0xFFFFFFFFu; g_stats[1] = 0u;
        g_stats[2] = 0u;          g_stats[3] = 0u;
        g_stats[4] = 0xFFFFFFFFu; g_stats[5] = 0u;
    }
}

// ---------------- fused stats: minmax(x) || absmax(W1) || absmax(W2) ----------------
static constexpr int STAT_BX = 4096;
static constexpr int STAT_BW = 1024;

__global__ void k_stats(const float4* __restrict__ x, int nx4,
                        const float4* __restrict__ w1, int n14,
                        const float4* __restrict__ w2, int n24) {
    const int b = blockIdx.x;
    __shared__ float sm[2][8];
    if (b < STAT_BX) {
        float lmin = 3.4e38f, lmax = -3.4e38f;
        for (int i = b * blockDim.x + threadIdx.x; i < nx4; i += STAT_BX * blockDim.x) {
            float4 v = x[i];
            lmin = fminf(lmin, fminf(fminf(v.x, v.y), fminf(v.z, v.w)));
            lmax = fmaxf(lmax, fmaxf(fmaxf(v.x, v.y), fmaxf(v.z, v.w)));
        }
        #pragma unroll
        for (int o = 16; o; o >>= 1) {
            lmin = fminf(lmin, __shfl_xor_sync(0xffffffffu, lmin, o));
            lmax = fmaxf(lmax, __shfl_xor_sync(0xffffffffu, lmax, o));
        }
        if ((threadIdx.x & 31) == 0) { sm[0][threadIdx.x >> 5] = lmin; sm[1][threadIdx.x >> 5] = lmax; }
        __syncthreads();
        if (threadIdx.x == 0) {
            float m = sm[0][0], M = sm[1][0];
            #pragma unroll
            for (int w = 1; w < 8; w++) { m = fminf(m, sm[0][w]); M = fmaxf(M, sm[1][w]); }
            atomicMin(&g_stats[0], fenc(m));
            atomicMax(&g_stats[1], fenc(M));
        }
    } else {
        const int which = (b < STAT_BX + STAT_BW) ? 0 : 1;
        const int b0 = which ? (STAT_BX + STAT_BW) : STAT_BX;
        const float4* w = which ? w2 : w1;
        const int n4 = which ? n24 : n14;
        const int slot = which ? 3 : 2;
        float lmax = 0.0f;
        for (int i = (b - b0) * blockDim.x + threadIdx.x; i < n4; i += STAT_BW * blockDim.x) {
            float4 v = w[i];
            lmax = fmaxf(lmax, fmaxf(fmaxf(fabsf(v.x), fabsf(v.y)), fmaxf(fabsf(v.z), fabsf(v.w))));
        }
        #pragma unroll
        for (int o = 16; o; o >>= 1) lmax = fmaxf(lmax, __shfl_xor_sync(0xffffffffu, lmax, o));
        if ((threadIdx.x & 31) == 0) sm[0][threadIdx.x >> 5] = lmax;
        __syncthreads();
        if (threadIdx.x == 0) {
            float M = sm[0][0];
            #pragma unroll
            for (int w2i = 1; w2i < 8; w2i++) M = fmaxf(M, sm[0][w2i]);
            atomicMax(&g_stats[slot], __float_as_uint(M));
        }
    }
}

// ---------------- finalize input/weight scales ----------------
__global__ void k_fin1() {
    if (threadIdx.x != 0) return;
    float an = fdec(g_stats[0]), ax = fdec(g_stats[1]);
    float sx = fmaxf(__fdiv_rn(ax - an, 255.0f), 1e-8f);
    float zxf = rintf(__fdiv_rn(-an, sx)) - 128.0f;
    zxf = fminf(fmaxf(zxf, -128.0f), 127.0f);
    float sw1 = fmaxf(__fdiv_rn(__uint_as_float(g_stats[2]), 127.0f), 1e-8f);
    float sw2 = fmaxf(__fdiv_rn(__uint_as_float(g_stats[3]), 127.0f), 1e-8f);
    g_scale[0] = sx; g_scale[1] = sw1; g_scale[2] = sw2;
    g_scale[3] = sx * sw1;
    g_zp[0] = (int)zxf;
}

// ---------------- finalize h scales (after GEMM1) ----------------
__global__ void k_fin2() {
    if (threadIdx.x != 0) return;
    float hn = fdec(g_stats[4]), hx = fdec(g_stats[5]);
    float sh = fmaxf(__fdiv_rn(hx - hn, 255.0f), 1e-8f);
    float zhf = rintf(__fdiv_rn(-hn, sh)) - 128.0f;
    zhf = fminf(fmaxf(zhf, -128.0f), 127.0f);
    g_scale[4] = sh;
    g_scale[5] = sh * g_scale[2];
    g_zp[1] = (int)zhf;
}

// ---------------- fused quantize: x || W1(+rs1) || W2(+rs2) ----------------
static constexpr int QA_BX = 2048;

__global__ void k_quant_all(const float4* __restrict__ x,
                            const float* __restrict__ W1,
                            const float* __restrict__ W2) {
    const int b = blockIdx.x;
    if (b < QA_BX) {
        const size_t n4 = (size_t)M_DIM * D_DIM / 4;
        char4* dst = (char4*)g_xq;
        float s = g_scale[0];
        float zp = (float)g_zp[0];
        for (size_t i = b * (size_t)blockDim.x + threadIdx.x; i < n4;
             i += (size_t)QA_BX * blockDim.x) {
            float4 v = x[i];
            float q0 = fminf(fmaxf(rintf(__fdiv_rn(v.x, s)) + zp, -128.0f), 127.0f);
            float q1 = fminf(fmaxf(rintf(__fdiv_rn(v.y, s)) + zp, -128.0f), 127.0f);
            float q2 = fminf(fmaxf(rintf(__fdiv_rn(v.z, s)) + zp, -128.0f), 127.0f);
            float q3 = fminf(fmaxf(rintf(__fdiv_rn(v.w, s)) + zp, -128.0f), 127.0f);
            char4 c; c.x = (char)(int)q0; c.y = (char)(int)q1; c.z = (char)(int)q2; c.w = (char)(int)q3;
            dst[i] = c;
        }
    } else {
        const int which = (b < QA_BX + H_DIM) ? 0 : 1;
        const int row = which ? (b - QA_BX - H_DIM) : (b - QA_BX);
        const int cols = which ? H_DIM : D_DIM;
        const float* W = which ? W2 : W1;
        int8_t* wq = which ? g_w2q : g_w1q;
        int* rs = which ? g_rs2 : g_rs1;
        float sw = which ? g_scale[2] : g_scale[1];
        const float4* src = (const float4*)(W + (size_t)row * cols);
        char4* dst = (char4*)(wq + (size_t)row * cols);
        int acc = 0;
        for (int c = threadIdx.x; c < (cols >> 2); c += blockDim.x) {
            float4 v = src[c];
            float q0 = fminf(fmaxf(rintf(__fdiv_rn(v.x, sw)), -127.0f), 127.0f);
            float q1 = fminf(fmaxf(rintf(__fdiv_rn(v.y, sw)), -127.0f), 127.0f);
            float q2 = fminf(fmaxf(rintf(__fdiv_rn(v.z, sw)), -127.0f), 127.0f);
            float q3 = fminf(fmaxf(rintf(__fdiv_rn(v.w, sw)), -127.0f), 127.0f);
            int i0 = (int)q0, i1 = (int)q1, i2 = (int)q2, i3 = (int)q3;
            acc += i0 + i1 + i2 + i3;
            char4 cc; cc.x = (char)i0; cc.y = (char)i1; cc.z = (char)i2; cc.w = (char)i3;
            dst[c] = cc;
        }
        #pragma unroll
        for (int o = 16; o; o >>= 1) acc += __shfl_xor_sync(0xffffffffu, acc, o);
        __shared__ int sm[8];
        if ((threadIdx.x & 31) == 0) sm[threadIdx.x >> 5] = acc;
        __syncthreads();
        if (threadIdx.x == 0) {
            int t = 0;
            #pragma unroll
            for (int w = 0; w < 8; w++) t += sm[w];
            rs[row] = t;
        }
    }
}

// ---------------- h quantize (fp32 -> int8), static MLP=4 schedule ----------------
// 4096 blocks x 256 thr = 2^20 threads; 16,777,216 float4 = exactly 16/thread.
// 4 batches of 4 independent strided loads each -> 4 loads in flight.
static constexpr int QH_BLOCKS = 4096;
static constexpr int QH_THREADS = 256;

__global__ void k_quant_h() {
    const float4* __restrict__ src = (const float4*)g_h;
    char4* __restrict__ dst = (char4*)g_hq;
    const float s = g_scale[4];
    const float zp = (float)g_zp[1];
    const size_t stride = (size_t)QH_BLOCKS * QH_THREADS;          // 2^20
    size_t i0 = (size_t)blockIdx.x * QH_THREADS + threadIdx.x;

    #pragma unroll
    for (int rep = 0; rep < 4; rep++) {
        const size_t base = i0 + (size_t)rep * 4 * stride;
        float4 v[4];
        #pragma unroll
        for (int j = 0; j < 4; j++) v[j] = src[base + (size_t)j * stride];
        #pragma unroll
        for (int j = 0; j < 4; j++) {
            float q0 = fminf(fmaxf(rintf(__fdiv_rn(v[j].x, s)) + zp, -128.0f), 127.0f);
            float q1 = fminf(fmaxf(rintf(__fdiv_rn(v[j].y, s)) + zp, -128.0f), 127.0f);
            float q2 = fminf(fmaxf(rintf(__fdiv_rn(v[j].z, s)) + zp, -128.0f), 127.0f);
            float q3 = fminf(fmaxf(rintf(__fdiv_rn(v[j].w, s)) + zp, -128.0f), 127.0f);
            char4 c; c.x = (char)(int)q0; c.y = (char)(int)q1; c.z = (char)(int)q2; c.w = (char)(int)q3;
            dst[base + (size_t)j * stride] = c;
        }
    }
}

// ========== hybrid int8 GEMM, templated M-tile (BM in {128, 64}) ==========
// kind 0 (mma):  16 warps, warp tile (BM/4)x32, 3-stage cp.async
// kind 1 (dp4a): BMx128 tile, K-transposed smem, 2-stage, spill-free
// kind = ((bn+bm)&7)<6 : mma 75% / dp4a 25% (measured optimum, R15).
static constexpr int SBN = 128;
static constexpr int SBK = 128;
static constexpr int NSTAGE = 3;
static constexpr int GTHREADS = 512;

template <int BM> struct GemmDims {
    static constexpr int IM = BM / 64;
    static constexpr int RPT = BM / 32;
    static constexpr int LOGBM = (BM == 128) ? 7 : 6;
    static constexpr int STAGE_A = BM * SBK;
    static constexpr int STAGE_SZ = STAGE_A + SBN * SBK;
    static constexpr int SMEM_DYN = 1024 + NSTAGE * STAGE_SZ;
    static constexpr int SDP = BM * 32 + 4096;
};

template <int MODE, int BM>
__global__ __launch_bounds__(GTHREADS, 2)
void k_gemm(const float* __restrict__ bias, int N, int K, float* __restrict__ outp) {
    using D = GemmDims<BM>;
    extern __shared__ char dsmem[];
    const int tid = threadIdx.x, wid = tid >> 5, lane = tid & 31;
    const int bm = blockIdx.y, bn = blockIdx.x;

    const int8_t* __restrict__ A = MODE ? g_xq : g_hq;
    const int8_t* __restrict__ B = MODE ? g_w1q : g_w2q;
    const int* __restrict__ rs   = MODE ? g_rs1 : g_rs2;
    float* __restrict__ out      = MODE ? g_h : outp;
    const float sc = MODE ? g_scale[3] : g_scale[5];
    const int   z  = MODE ? g_zp[0] : g_zp[1];

    const uint32_t base0 = smem_u32(dsmem);
    const uint32_t tiles = (base0 + 1023) & ~1023u;
    const int KT = K >> 7;

    const int kind = (((bn + bm) & 7) < 6) ? 0 : 1;

    float lmin = 3.4e38f, lmax = -3.4e38f;

    if (kind == 0) {
        // ================= mma path =================
        const int warp_m = wid & 3;
        const int warp_n = wid >> 2;

        uint32_t offA[D::IM], offB[2];
        {
            int rbase = warp_m * (BM / 4) + (lane & 7) + ((lane >> 3) & 1) * 8;
            int cA = ((lane >> 4) & 1) * 16;
            #pragma unroll
            for (int im = 0; im < D::IM; im++) {
                int row = rbase + im * 16;
                offA[im] = SWZ((uint32_t)(row * 128 + cA));
            }
            int nbase = warp_n * 32 + (lane & 7) + ((lane >> 4) & 1) * 8;
            int cB = ((lane >> 3) & 1) * 16;
            #pragma unroll
            for (int ig = 0; ig < 2; ig++) {
                int row = nbase + ig * 16;
                offB[ig] = SWZ((uint32_t)(row * 128 + cB));
            }
        }

        int c[D::IM][4][4];
        #pragma unroll
        for (int i = 0; i < D::IM; i++)
            #pragma unroll
            for (int j = 0; j < 4; j++)
                #pragma unroll
                for (int k = 0; k < 4; k++) c[i][j][k] = 0;

        auto load_stage = [&](int s, int kt) {
            uint32_t abase = tiles + s * D::STAGE_SZ;
            uint32_t bbase = abase + D::STAGE_A;
            const int8_t* Ag = A + (size_t)(bm * BM) * K + (size_t)kt * SBK;
            const int8_t* Bg = B + (size_t)(bn * SBN) * K + (size_t)kt * SBK;
            #pragma unroll
            for (int i = 0; i < D::IM; i++) {
                int idx = tid + i * GTHREADS;
                int row = idx >> 3, cc2 = (idx & 7) * 16;
                CP_ASYNC16(abase + SWZ((uint32_t)(row * 128 + cc2)), Ag + (size_t)row * K + cc2);
            }
            #pragma unroll
            for (int i = 0; i < 2; i++) {
                int idx = tid + i * GTHREADS;
                int row = idx >> 3, cc2 = (idx & 7) * 16;
                CP_ASYNC16(bbase + SWZ((uint32_t)(row * 128 + cc2)), Bg + (size_t)row * K + cc2);
            }
        };

        load_stage(0, 0); CP_COMMIT();
        load_stage(1, 1); CP_COMMIT();

        for (int kt = 0; kt < KT; kt++) {
            const int s = kt - (kt / NSTAGE) * NSTAGE;
            CP_WAIT1();
            __syncthreads();

            const uint32_t abase = tiles + s * D::STAGE_SZ;
            const uint32_t bbase = abase + D::STAGE_A;
            #pragma unroll
            for (int kk = 0; kk < SBK; kk += 32) {
                uint32_t a[D::IM][4], b[4][2];
                #pragma unroll
                for (int im = 0; im < D::IM; im++)
                    LDSM_X4(a[im][0], a[im][1], a[im][2], a[im][3], (abase + offA[im]) ^ kk);
                #pragma unroll
                for (int ig = 0; ig < 2; ig++)
                    LDSM_X4(b[2 * ig][0], b[2 * ig][1], b[2 * ig + 1][0], b[2 * ig + 1][1],
                            (bbase + offB[ig]) ^ kk);
                #pragma unroll
                for (int im = 0; im < D::IM; im++)
                    #pragma unroll
                    for (int in = 0; in < 4; in++)
                        mma_s8(c[im][in], a[im], b[in]);
            }

            const int nk = kt + 2;
            if (nk < KT) {
                const int ns = nk - (nk / NSTAGE) * NSTAGE;
                load_stage(ns, nk);
            }
            CP_COMMIT();
        }

        // epilogue (mma)
        #pragma unroll
        for (int in = 0; in < 4; in++) {
            int col = bn * SBN + warp_n * 32 + in * 8 + (lane & 3) * 2;
            int rs0 = rs[col], rs1v = rs[col + 1];
            float b0 = bias[col], b1v = bias[col + 1];
            #pragma unroll
            for (int im = 0; im < D::IM; im++) {
                int row = bm * BM + warp_m * (BM / 4) + im * 16 + (lane >> 2);
                float v0 = (float)(c[im][in][0] - z * rs0) * sc + b0;
                float v1 = (float)(c[im][in][1] - z * rs1v) * sc + b1v;
                float v2 = (float)(c[im][in][2] - z * rs0) * sc + b0;
                float v3 = (float)(c[im][in][3] - z * rs1v) * sc + b1v;
                if (MODE) {
                    v0 = gelu_exact(v0); v1 = gelu_exact(v1);
                    v2 = gelu_exact(v2); v3 = gelu_exact(v3);
                    lmin = fminf(lmin, fminf(fminf(v0, v1), fminf(v2, v3)));
                    lmax = fmaxf(lmax, fmaxf(fmaxf(v0, v1), fmaxf(v2, v3)));
                }
                *(float2*)(out + (size_t)row * N + col) = make_float2(v0, v1);
                *(float2*)(out + (size_t)(row + 8) * N + col) = make_float2(v2, v3);
            }
        }
    } else {
        // ================= dp4a path (spill-free) =================
        uint32_t* sbase = (uint32_t*)(dsmem + (int)(tiles - base0));
        const int wm = wid >> 2, wn = wid & 3;
        const int r0 = wm * (BM / 4) + (lane & 7) * D::RPT;
        const int c0 = wn * 32 + (lane >> 3) * 8;

        auto load_tr = [&](int kt, int s) {
            uint32_t* At = sbase + s * D::SDP;
            uint32_t* Bt = At + BM * 32;
            #pragma unroll
            for (int i = 0; i < D::IM; i++) {
                int idx = tid + i * GTHREADS;
                int r = idx & (BM - 1), c16 = idx >> D::LOGBM;
                uint4 va = *(const uint4*)(A + (size_t)(bm * BM + r) * K + kt * SBK + c16 * 16);
                int k4 = c16 * 4;
                At[(k4 + 0) * BM + r] = va.x; At[(k4 + 1) * BM + r] = va.y;
                At[(k4 + 2) * BM + r] = va.z; At[(k4 + 3) * BM + r] = va.w;
            }
            #pragma unroll
            for (int i = 0; i < 2; i++) {
                int idx = tid + i * GTHREADS;
                int r = idx & 127, c16 = idx >> 7;
                uint4 vb = *(const uint4*)(B + (size_t)(bn * SBN + r) * K + kt * SBK + c16 * 16);
                int k4 = c16 * 4;
                Bt[(k4 + 0) * 128 + r] = vb.x; Bt[(k4 + 1) * 128 + r] = vb.y;
                Bt[(k4 + 2) * 128 + r] = vb.z; Bt[(k4 + 3) * 128 + r] = vb.w;
            }
        };

        int acc[D::RPT][8];
        #pragma unroll
        for (int i = 0; i < D::RPT; i++)
            #pragma unroll
            for (int j = 0; j < 8; j++) acc[i][j] = 0;

        load_tr(0, 0);
        __syncthreads();

        for (int kt = 0; kt < KT; kt++) {
            const uint32_t* At = sbase + (kt & 1) * D::SDP;
            const uint32_t* Bt = At + BM * 32;
            #pragma unroll 8
            for (int k4 = 0; k4 < 32; k4++) {
                int a[D::RPT];
                if constexpr (BM == 128) {
                    uint4 a4 = *(const uint4*)(At + k4 * BM + r0);
                    a[0] = (int)a4.x; a[1] = (int)a4.y; a[2] = (int)a4.z; a[3] = (int)a4.w;
                } else {
                    uint2 a2 = *(const uint2*)(At + k4 * BM + r0);
                    a[0] = (int)a2.x; a[1] = (int)a2.y;
                }
                uint4 b4 = *(const uint4*)(Bt + k4 * 128 + c0);
                uint4 b5 = *(const uint4*)(Bt + k4 * 128 + c0 + 4);
                int b[8] = {(int)b4.x, (int)b4.y, (int)b4.z, (int)b4.w,
                            (int)b5.x, (int)b5.y, (int)b5.z, (int)b5.w};
                #pragma unroll
                for (int i = 0; i < D::RPT; i++)
                    #pragma unroll
                    for (int j = 0; j < 8; j++)
                        acc[i][j] = dp4a(a[i], b[j], acc[i][j]);
            }
            if (kt + 1 < KT) load_tr(kt + 1, (kt + 1) & 1);
            __syncthreads();
        }

        // epilogue (dp4a)
        const int col0 = bn * SBN + c0;
        int zr[8]; float bb[8];
        #pragma unroll
        for (int j = 0; j < 8; j++) { zr[j] = z * rs[col0 + j]; bb[j] = bias[col0 + j]; }
        #pragma unroll
        for (int i = 0; i < D::RPT; i++) {
            size_t ro = (size_t)(bm * BM + r0 + i) * N + col0;
            float v[8];
            #pragma unroll
            for (int j = 0; j < 8; j++) {
                float f = (float)(acc[i][j] - zr[j]) * sc + bb[j];
                if (MODE) {
                    f = gelu_exact(f);
                    lmin = fminf(lmin, f);
                    lmax = fmaxf(lmax, f);
                }
                v[j] = f;
            }
            *(float4*)(out + ro)     = make_float4(v[0], v[1], v[2], v[3]);
            *(float4*)(out + ro + 4) = make_float4(v[4], v[5], v[6], v[7]);
        }
    }

    // ---- common min/max reduction (MODE 1) ----
    if (MODE) {
        #pragma unroll
        for (int o = 16; o; o >>= 1) {
            lmin = fminf(lmin, __shfl_xor_sync(0xffffffffu, lmin, o));
            lmax = fmaxf(lmax, __shfl_xor_sync(0xffffffffu, lmax, o));
        }
        __shared__ float red[2][16];
        if (lane == 0) { red[0][wid] = lmin; red[1][wid] = lmax; }
        __syncthreads();
        if (tid == 0) {
            float m = red[0][0], Mx = red[1][0];
            #pragma unroll
            for (int w = 1; w < 16; w++) { m = fminf(m, red[0][w]); Mx = fmaxf(Mx, red[1][w]); }
            atomicMin(&g_stats[4], fenc(m));
            atomicMax(&g_stats[5], fenc(Mx));
        }
    }
}

// ---------------- launch ----------------
extern "C" void kernel_launch(void* const* d_in, const int* in_sizes, int n_in,
                              void* d_out, int out_size) {
    const float* x  = (const float*)d_in[0];
    const float* W1 = (const float*)d_in[1];
    const float* b1 = (const float*)d_in[2];
    const float* W2 = (const float*)d_in[3];
    const float* b2 = (const float*)d_in[4];
    float* out = (float*)d_out;

    const size_t nx = (size_t)M_DIM * D_DIM;

    cudaFuncSetAttribute(k_gemm<1, 128>, cudaFuncAttributeMaxDynamicSharedMemorySize,
                         GemmDims<128>::SMEM_DYN);
    cudaFuncSetAttribute(k_gemm<0, 64>, cudaFuncAttributeMaxDynamicSharedMemorySize,
                         GemmDims<64>::SMEM_DYN);

    k_init<<<1, 32>>>();

    k_stats<<<STAT_BX + 2 * STAT_BW, 256>>>(
        (const float4*)x, (int)(nx / 4),
        (const float4*)W1, (int)((size_t)H_DIM * D_DIM / 4),
        (const float4*)W2, (int)((size_t)D_DIM * H_DIM / 4));
    k_fin1<<<1, 32>>>();

    k_quant_all<<<QA_BX + H_DIM + D_DIM, 256>>>((const float4*)x, W1, W2);

    // GEMM1: 128x128 tiles -> gelu -> g_h (fp32) + h min/max; 75/25 hybrid
    dim3 g1(H_DIM / SBN, M_DIM / 128);   // (32, 128)
    k_gemm<1, 128><<<g1, GTHREADS, GemmDims<128>::SMEM_DYN>>>(b1, H_DIM, D_DIM, nullptr);

    k_fin2<<<1, 32>>>();
    k_quant_h<<<QH_BLOCKS, QH_THREADS>>>();

    // GEMM2: 64x128 tiles (wave-quantization fix, R12); 75/25 hybrid
    dim3 g2(D_DIM / SBN, M_DIM / 64);    // (8, 256)
    k_gemm<0, 64><<<g2, GTHREADS, GemmDims<64>::SMEM_DYN>>>(b2, D_DIM, H_DIM, out);
}